// round 10
// baseline (speedup 1.0000x reference)
#include <cuda_runtime.h>
#include <cuda_fp16.h>
#include <cstdint>

// SGIntoKGPool via mma.sync m16n8k16 fp16 (base PTX, safe on compute_103).
// out[b,m,c] = (sum_n adj[b,n,m] * x[b,c,n]) / max(sum_n adj[b,n,m], 1)
// B=8, C=64, N=4096, M=2048.
// Round 10: fp16 k16 MMA (half the B-load instrs of tf32 k8), A panels in
// fragment order staged via cp.async ring + LDS.128, B via LDG->cvt->STS->
// ldmatrix.trans, exact fp32 degrees, one barrier per tile.

#define BZv 8
#define Cv  64
#define Nv  4096
#define Mv  2048
#define KT  64
#define NTl (Nv / KT)       // 64 k-tiles
#define MTm 64              // m-tile

#define APANEL   16384       // A tile panel bytes (hi+lo fragment order)
#define BSTRIDE  160         // bytes per B smem row (64 halfs + 16B pad)
#define BBUF     (KT * BSTRIDE)             // 10240
#define OFF_B    (3 * APANEL)               // 49152
#define OFF_DEGS (OFF_B + 2 * BBUF)         // 69632
#define OFF_INVS (OFF_DEGS + 256)           // 69888
#define SMEMB    (OFF_INVS + 256)           // 70144 (dynamic)

// x hi/lo fp16 fragment panels: per (b,kt): 32 groups x 32 lanes x uint4 = 16KB
// group g = (hilo*4 + cblk)*4 + kstep
__device__ uint4 g_A[BZv * NTl * 1024];     // 8 MB

__device__ __forceinline__ uint32_t smem_u32(const void* p) {
    uint32_t a;
    asm("{ .reg .u64 t; cvta.to.shared.u64 t, %1; cvt.u32.u64 %0, t; }" : "=r"(a) : "l"(p));
    return a;
}
__device__ __forceinline__ void cp16(uint32_t saddr, const void* gaddr) {
    asm volatile("cp.async.cg.shared.global [%0], [%1], 16;" :: "r"(saddr), "l"(gaddr));
}
__device__ __forceinline__ uint4 lds128(uint32_t a) {
    uint4 v;
    asm volatile("ld.shared.v4.u32 {%0,%1,%2,%3}, [%4];"
                 : "=r"(v.x), "=r"(v.y), "=r"(v.z), "=r"(v.w) : "r"(a));
    return v;
}
__device__ __forceinline__ void ldsm4t(uint32_t (&r)[4], uint32_t a) {
    asm volatile("ldmatrix.sync.aligned.m8n8.x4.trans.shared.b16 {%0,%1,%2,%3}, [%4];"
                 : "=r"(r[0]), "=r"(r[1]), "=r"(r[2]), "=r"(r[3]) : "r"(a));
}
__device__ __forceinline__ void mma16816(float (&d)[4], const uint4& a,
                                         uint32_t b0, uint32_t b1) {
    asm volatile("mma.sync.aligned.m16n8k16.row.col.f32.f16.f16.f32 "
                 "{%0,%1,%2,%3}, {%4,%5,%6,%7}, {%8,%9}, {%0,%1,%2,%3};"
                 : "+f"(d[0]), "+f"(d[1]), "+f"(d[2]), "+f"(d[3])
                 : "r"(a.x), "r"(a.y), "r"(a.z), "r"(a.w), "r"(b0), "r"(b1));
}
__device__ __forceinline__ unsigned packh2(float v0, float v1) {
    __half h0 = __float2half_rn(v0), h1 = __float2half_rn(v1);
    return (unsigned)__half_as_ushort(h0) | ((unsigned)__half_as_ushort(h1) << 16);
}
__device__ __forceinline__ unsigned pack_hl(float a, float b, unsigned& lo) {
    __half ha = __float2half_rn(a), hb = __float2half_rn(b);
    lo = packh2(a - __half2float(ha), b - __half2float(hb));
    return (unsigned)__half_as_ushort(ha) | ((unsigned)__half_as_ushort(hb) << 16);
}

// ---------------- prep: x -> fp16 hi/lo fragment panels ----------------
// m16n8k16 A fragment: lane l holds rows {g, g+8} (g=l>>2), cols {2t,2t+1, +8} (t=l&3)
__global__ __launch_bounds__(256)
void prep_A(const float* __restrict__ x) {
    unsigned gid   = blockIdx.x * 256 + threadIdx.x;   // 262144 threads
    unsigned lid   = gid & 31;
    unsigned kstep = (gid >> 5) & 3;
    unsigned cblk  = (gid >> 7) & 3;
    unsigned kt    = (gid >> 9) & (NTl - 1);
    unsigned b     = gid >> 15;

    int r0 = cblk * 16 + (lid >> 2);                   // c row
    const float* px = x + ((size_t)b * Cv + r0) * Nv + kt * KT + kstep * 16 + (lid & 3) * 2;

    uint4 hi, lo;
    hi.x = pack_hl(px[0],            px[1],            lo.x);
    hi.y = pack_hl(px[8 * Nv],       px[8 * Nv + 1],   lo.y);
    hi.z = pack_hl(px[8],            px[9],            lo.z);
    hi.w = pack_hl(px[8 * Nv + 8],   px[8 * Nv + 9],   lo.w);

    size_t base = ((size_t)(b * NTl + kt) << 10) + lid;
    g_A[base + ((0 + cblk) * 4 + kstep) * 32] = hi;    // hilo=0
    g_A[base + ((4 + cblk) * 4 + kstep) * 32] = lo;    // hilo=1
}

// ---------------- main kernel ----------------
__global__ __launch_bounds__(256, 2)
void sg_kg_fp16(const float* __restrict__ adj, float* __restrict__ out) {
    extern __shared__ __align__(16) char smem[];
    const int tid = threadIdx.x;
    const int lid = tid & 31, wid = tid >> 5;
    const int b = blockIdx.y, m0 = blockIdx.x * MTm;
    const int wr = wid & 1;          // c dir: 2 warps x 32 rows
    const int wc = wid >> 1;         // m dir: 4 warps x 16 cols
    const uint32_t sb = smem_u32(smem);

    // adj convert lane mapping: thread owns row kcp, m = c16*16 .. +15
    const int kcp = tid >> 2;        // 0..63
    const int c16 = tid & 3;
    const float* adjb = adj + (size_t)b * Nv * Mv + m0 + c16 * 16;

    const char* Agm = (const char*)g_A + (size_t)(b * NTl) * APANEL + tid * 16;

    float* degS = (float*)(smem + OFF_DEGS);
    float* invS = (float*)(smem + OFF_INVS);
    if (tid < MTm) degS[tid] = 0.0f;

    float acc[2][2][4];
    #pragma unroll
    for (int i = 0; i < 2; i++)
        #pragma unroll
        for (int j = 0; j < 2; j++)
            #pragma unroll
            for (int p = 0; p < 4; p++) acc[i][j][p] = 0.f;
    float dacc[16];
    #pragma unroll
    for (int j = 0; j < 16; j++) dacc[j] = 0.f;

    // cp.async of one A panel: 4 x 16B per thread
    auto issueA = [&](int t, int slot) {
        const char* g = Agm + (size_t)t * APANEL;
        uint32_t s = sb + slot * APANEL + tid * 16;
        cp16(s,            g);
        cp16(s + 4096,     g + 4096);
        cp16(s + 8192,     g + 8192);
        cp16(s + 12288,    g + 12288);
        asm volatile("cp.async.commit_group;" ::: "memory");
    };

    // B per-warp addresses
    const uint32_t bl_off = (uint32_t)((lid & 15) * BSTRIDE + (wc * 16 + (lid >> 4) * 8) * 2);
    const uint32_t bs_off = (uint32_t)(kcp * BSTRIDE + c16 * 32);
    // A per-warp fragment byte offsets (group*512 + lid*16)
    const uint32_t ah0 = (uint32_t)(((wr * 2 + 0) * 4) * 512 + lid * 16);
    const uint32_t ah1 = ah0 + 2048;          // cblk +1
    // lo groups: +16 groups = +8192 bytes

    float4 fr[4];                    // adj prefetch (16 floats)
    auto loadAdj = [&](int t) {
        const float* g = adjb + (size_t)t * KT * Mv + (size_t)kcp * Mv;
        fr[0] = *(const float4*)(g);
        fr[1] = *(const float4*)(g + 4);
        fr[2] = *(const float4*)(g + 8);
        fr[3] = *(const float4*)(g + 12);
    };
    auto stageB = [&](int bufsel) {
        #pragma unroll
        for (int i = 0; i < 4; i++) {
            dacc[i * 4 + 0] += fr[i].x; dacc[i * 4 + 1] += fr[i].y;
            dacc[i * 4 + 2] += fr[i].z; dacc[i * 4 + 3] += fr[i].w;
        }
        uint32_t s = sb + OFF_B + bufsel * BBUF + bs_off;
        uint4 w0 = make_uint4(packh2(fr[0].x, fr[0].y), packh2(fr[0].z, fr[0].w),
                              packh2(fr[1].x, fr[1].y), packh2(fr[1].z, fr[1].w));
        uint4 w1 = make_uint4(packh2(fr[2].x, fr[2].y), packh2(fr[2].z, fr[2].w),
                              packh2(fr[3].x, fr[3].y), packh2(fr[3].z, fr[3].w));
        asm volatile("st.shared.v4.b32 [%0], {%1,%2,%3,%4};"
                     :: "r"(s), "r"(w0.x), "r"(w0.y), "r"(w0.z), "r"(w0.w) : "memory");
        asm volatile("st.shared.v4.b32 [%0], {%1,%2,%3,%4};"
                     :: "r"(s + 16), "r"(w1.x), "r"(w1.y), "r"(w1.z), "r"(w1.w) : "memory");
    };

    // prologue: B tile 0 staged, A slots 0,1 in flight
    loadAdj(0);
    stageB(0);
    issueA(0, 0);
    issueA(1, 1);

    int slot = 0;   // A ring slot for tile t
    for (int t = 0; t < NTl; t++) {
        if (t == NTl - 1) asm volatile("cp.async.wait_group 0;" ::: "memory");
        else              asm volatile("cp.async.wait_group 1;" ::: "memory");
        __syncthreads();   // A(t) + B(t) visible; all reads of previous buffers done

        if (t + 1 < NTl) loadAdj(t + 1);                        // fires early
        if (t + 2 < NTl) {
            int ns = slot + 2; if (ns >= 3) ns -= 3;
            issueA(t + 2, ns);
        }

        const uint32_t sA = sb + slot * APANEL;
        const uint32_t sB = sb + OFF_B + (t & 1) * BBUF + bl_off;

        #pragma unroll
        for (int ks = 0; ks < 4; ks++) {
            uint32_t bb[4];
            ldsm4t(bb, sB + ks * (16 * BSTRIDE));
            uint4 h0 = lds128(sA + ah0 + ks * 512);
            uint4 h1 = lds128(sA + ah1 + ks * 512);
            uint4 l0 = lds128(sA + ah0 + 8192 + ks * 512);
            uint4 l1 = lds128(sA + ah1 + 8192 + ks * 512);
            mma16816(acc[0][0], h0, bb[0], bb[1]); mma16816(acc[0][1], h0, bb[2], bb[3]);
            mma16816(acc[1][0], h1, bb[0], bb[1]); mma16816(acc[1][1], h1, bb[2], bb[3]);
            mma16816(acc[0][0], l0, bb[0], bb[1]); mma16816(acc[0][1], l0, bb[2], bb[3]);
            mma16816(acc[1][0], l1, bb[0], bb[1]); mma16816(acc[1][1], l1, bb[2], bb[3]);
        }

        if (t + 1 < NTl) stageB((t + 1) & 1);   // writes buf^1: its readers passed barrier
        slot++; if (slot == 3) slot = 0;
    }

    // ---- degrees: exact fp32, smem atomic reduction ----
    __syncthreads();   // all smem reads of the loop complete
    #pragma unroll
    for (int j = 0; j < 16; j++)
        atomicAdd(&degS[c16 * 16 + j], dacc[j]);

    // ---- stage accumulators (outS aliases A ring; compute done) ----
    float* outS = (float*)smem;   // [m][c], stride 68 floats (17408 B)
    #pragma unroll
    for (int ci = 0; ci < 2; ci++) {
        #pragma unroll
        for (int nb = 0; nb < 2; nb++) {
            int c_row = wr * 32 + ci * 16 + (lid >> 2);
            int m_col = wc * 16 + nb * 8 + (lid & 3) * 2;
            outS[m_col * 68 + c_row]           = acc[ci][nb][0];
            outS[(m_col + 1) * 68 + c_row]     = acc[ci][nb][1];
            outS[m_col * 68 + c_row + 8]       = acc[ci][nb][2];
            outS[(m_col + 1) * 68 + c_row + 8] = acc[ci][nb][3];
        }
    }
    __syncthreads();
    if (tid < MTm) invS[tid] = 1.0f / fmaxf(degS[tid], 1.0f);
    __syncthreads();

    // ---- scaled float4 stores ----
    float* Og = out + ((size_t)b * Mv + m0) * Cv;
    #pragma unroll
    for (int i = 0; i < 4; i++) {
        int idx = tid + i * 256;                 // 1024 float4s
        int ml = idx >> 4, c4 = (idx & 15) * 4;
        float4 v = *(float4*)(outS + ml * 68 + c4);
        float inv = invS[ml];
        v.x *= inv; v.y *= inv; v.z *= inv; v.w *= inv;
        *(float4*)(Og + (size_t)ml * Cv + c4) = v;
    }
}

extern "C" void kernel_launch(void* const* d_in, const int* in_sizes, int n_in,
                              void* d_out, int out_size)
{
    const float* x;
    const float* adj;
    if (in_sizes[0] == BZv * Cv * Nv) {
        x   = (const float*)d_in[0];
        adj = (const float*)d_in[1];
    } else {
        x   = (const float*)d_in[1];
        adj = (const float*)d_in[0];
    }
    float* out = (float*)d_out;

    cudaFuncSetAttribute(sg_kg_fp16, cudaFuncAttributeMaxDynamicSharedMemorySize, SMEMB);

    prep_A<<<1024, 256>>>(x);                                     // 262144 threads
    sg_kg_fp16<<<dim3(Mv / MTm, BZv), 256, SMEMB>>>(adj, out);    // 256 CTAs
}

// round 11
// speedup vs baseline: 1.3250x; 1.3250x over previous
#include <cuda_runtime.h>
#include <cuda_fp16.h>
#include <cstdint>

// SGIntoKGPool via mma.sync m16n8k16 fp16 (base PTX, safe on compute_103).
// out[b,m,c] = (sum_n adj[b,n,m] * x[b,c,n]) / max(sum_n adj[b,n,m], 1)
// B=8, C=64, N=4096, M=2048.
// Round 11: warp tiling 4c x 2m (half the A redundancy), A fragments direct
// LDG from fragment-order panels with full-tile refill slack (8-slot ring),
// B = adj LDG -> fp32 degrees -> fp16 cvt -> STS -> ldmatrix.trans.
// One barrier per tile, static 18.7KB smem, 2 CTAs/SM.

#define BZv 8
#define Cv  64
#define Nv  4096
#define Mv  2048
#define KT  64
#define NTl (Nv / KT)       // 64 k-tiles
#define MTm 64              // m-tile

#define APANEL   16384       // A tile panel bytes (hi+lo fragment order)
#define BSTRIDE  144         // bytes per B smem row (64 halfs + 16B pad; 16B-aligned)
#define BBUF     (KT * BSTRIDE)             // 9216
#define OFF_DEGS (2 * BBUF)                 // 18432
#define SMEMB    (OFF_DEGS + 256)           // 18688 (static)

// x hi/lo fp16 fragment panels: per (b,kt): 32 groups x 32 lanes x uint4 = 16KB
// group g = (hilo*4 + cblk)*4 + kstep
__device__ uint4 g_A[BZv * NTl * 1024];     // 8 MB

__device__ __forceinline__ uint32_t smem_u32(const void* p) {
    uint32_t a;
    asm("{ .reg .u64 t; cvta.to.shared.u64 t, %1; cvt.u32.u64 %0, t; }" : "=r"(a) : "l"(p));
    return a;
}
__device__ __forceinline__ void ldsm4t(uint32_t (&r)[4], uint32_t a) {
    asm volatile("ldmatrix.sync.aligned.m8n8.x4.trans.shared.b16 {%0,%1,%2,%3}, [%4];"
                 : "=r"(r[0]), "=r"(r[1]), "=r"(r[2]), "=r"(r[3]) : "r"(a));
}
__device__ __forceinline__ void mma16816(float (&d)[4], const uint4& a,
                                         uint32_t b0, uint32_t b1) {
    asm volatile("mma.sync.aligned.m16n8k16.row.col.f32.f16.f16.f32 "
                 "{%0,%1,%2,%3}, {%4,%5,%6,%7}, {%8,%9}, {%0,%1,%2,%3};"
                 : "+f"(d[0]), "+f"(d[1]), "+f"(d[2]), "+f"(d[3])
                 : "r"(a.x), "r"(a.y), "r"(a.z), "r"(a.w), "r"(b0), "r"(b1));
}
__device__ __forceinline__ unsigned packh2(float v0, float v1) {
    __half h0 = __float2half_rn(v0), h1 = __float2half_rn(v1);
    return (unsigned)__half_as_ushort(h0) | ((unsigned)__half_as_ushort(h1) << 16);
}
__device__ __forceinline__ unsigned pack_hl(float a, float b, unsigned& lo) {
    __half ha = __float2half_rn(a), hb = __float2half_rn(b);
    lo = packh2(a - __half2float(ha), b - __half2float(hb));
    return (unsigned)__half_as_ushort(ha) | ((unsigned)__half_as_ushort(hb) << 16);
}
__device__ __forceinline__ void sts128(uint32_t a, uint4 v) {
    asm volatile("st.shared.v4.b32 [%0], {%1,%2,%3,%4};"
                 :: "r"(a), "r"(v.x), "r"(v.y), "r"(v.z), "r"(v.w) : "memory");
}

// ---------------- prep: x -> fp16 hi/lo fragment panels ----------------
// m16n8k16 A fragment: lane l holds rows {g, g+8} (g=l>>2), cols {2t,2t+1, +8} (t=l&3)
__global__ __launch_bounds__(256)
void prep_A(const float* __restrict__ x) {
    unsigned gid   = blockIdx.x * 256 + threadIdx.x;   // 262144 threads
    unsigned lid   = gid & 31;
    unsigned kstep = (gid >> 5) & 3;
    unsigned cblk  = (gid >> 7) & 3;
    unsigned kt    = (gid >> 9) & (NTl - 1);
    unsigned b     = gid >> 15;

    int r0 = cblk * 16 + (lid >> 2);                   // c row
    const float* px = x + ((size_t)b * Cv + r0) * Nv + kt * KT + kstep * 16 + (lid & 3) * 2;

    uint4 hi, lo;
    hi.x = pack_hl(px[0],            px[1],            lo.x);
    hi.y = pack_hl(px[8 * Nv],       px[8 * Nv + 1],   lo.y);
    hi.z = pack_hl(px[8],            px[9],            lo.z);
    hi.w = pack_hl(px[8 * Nv + 8],   px[8 * Nv + 9],   lo.w);

    size_t base = ((size_t)(b * NTl + kt) << 10) + lid;
    g_A[base + ((0 + cblk) * 4 + kstep) * 32] = hi;    // hilo=0
    g_A[base + ((4 + cblk) * 4 + kstep) * 32] = lo;    // hilo=1
}

// ---------------- main kernel ----------------
__global__ __launch_bounds__(256, 2)
void sg_kg_fp16(const float* __restrict__ adj, float* __restrict__ out) {
    __shared__ __align__(16) char smem[SMEMB];
    const int tid = threadIdx.x;
    const int lid = tid & 31, wid = tid >> 5;
    const int b = blockIdx.y, m0 = blockIdx.x * MTm;
    const int cblk = wid & 3;        // c dir: 4 warps x 16 rows
    const int wc   = wid >> 2;       // m dir: 2 warps x 32 cols
    const uint32_t sb = smem_u32(smem);

    // adj lane mapping: thread owns k-row kcp, m chunk c16*16..+15
    const int kcp = tid >> 2;        // 0..63
    const int c16 = tid & 3;
    const float* adjb = adj + (size_t)b * Nv * Mv + m0 + c16 * 16;

    const char* Apan = (const char*)g_A + (size_t)(b * NTl) * APANEL + lid * 16;

    float* degS = (float*)(smem + OFF_DEGS);
    if (tid < MTm) degS[tid] = 0.0f;

    float acc[4][4];
    #pragma unroll
    for (int j = 0; j < 4; j++)
        #pragma unroll
        for (int p = 0; p < 4; p++) acc[j][p] = 0.f;
    float dacc[16];
    #pragma unroll
    for (int j = 0; j < 16; j++) dacc[j] = 0.f;

    // B ldsm per-thread offset within a buffer (+ks*16 rows per k-step)
    const uint32_t bl = (uint32_t)((lid & 15) * BSTRIDE + (wc * 32 + (lid >> 4) * 8) * 2);
    // A fragment byte offsets: group g = (hilo*4 + cblk)*4 + ks, offset g*512
    const uint32_t aghi = (uint32_t)(cblk * 4) * 512;          // +ks*512
    const uint32_t aglo = (uint32_t)(16 + cblk * 4) * 512;

    float4 fr[4];                    // adj prefetch (16 floats)
    auto loadAdj = [&](int t) {
        const float* g = adjb + (size_t)(t * KT + kcp) * Mv;
        fr[0] = *(const float4*)(g);
        fr[1] = *(const float4*)(g + 4);
        fr[2] = *(const float4*)(g + 8);
        fr[3] = *(const float4*)(g + 12);
    };
    auto stageB = [&](int bufsel) {
        #pragma unroll
        for (int i = 0; i < 4; i++) {
            dacc[i * 4 + 0] += fr[i].x; dacc[i * 4 + 1] += fr[i].y;
            dacc[i * 4 + 2] += fr[i].z; dacc[i * 4 + 3] += fr[i].w;
        }
        uint32_t s = sb + bufsel * BBUF + kcp * BSTRIDE + c16 * 32;
        uint4 w0 = make_uint4(packh2(fr[0].x, fr[0].y), packh2(fr[0].z, fr[0].w),
                              packh2(fr[1].x, fr[1].y), packh2(fr[1].z, fr[1].w));
        uint4 w1 = make_uint4(packh2(fr[2].x, fr[2].y), packh2(fr[2].z, fr[2].w),
                              packh2(fr[3].x, fr[3].y), packh2(fr[3].z, fr[3].w));
        sts128(s, w0);
        sts128(s + 16, w1);
    };

    // A-fragment ring: slot s = ks*2 + hilo, holds current tile's frags
    uint4 afr[8];
    {
        const char* A0 = Apan;       // tile 0
        #pragma unroll
        for (int ks = 0; ks < 4; ks++) {
            afr[ks * 2]     = *(const uint4*)(A0 + aghi + ks * 512);
            afr[ks * 2 + 1] = *(const uint4*)(A0 + aglo + ks * 512);
        }
    }

    // prologue
    loadAdj(0);
    stageB(0);
    __syncthreads();
    loadAdj(1);

    for (int t = 0; t < NTl; t++) {
        if (t + 2 < NTl) { /* fr for t+1 already loaded; nothing here */ }

        const char* Anext = Apan + (size_t)((t + 1 < NTl) ? t + 1 : t) * APANEL;
        const uint32_t sB = sb + (t & 1) * BBUF + bl;

        #pragma unroll
        for (int ks = 0; ks < 4; ks++) {
            uint32_t bb0[4], bb1[4];
            ldsm4t(bb0, sB + ks * (16 * BSTRIDE));         // n 0..15 of warp half
            ldsm4t(bb1, sB + ks * (16 * BSTRIDE) + 32);    // n 16..31
            uint4 hi = afr[ks * 2], lo = afr[ks * 2 + 1];
            // refill with next tile's same-slot frags (full-tile slack)
            afr[ks * 2]     = *(const uint4*)(Anext + aghi + ks * 512);
            afr[ks * 2 + 1] = *(const uint4*)(Anext + aglo + ks * 512);
            mma16816(acc[0], hi, bb0[0], bb0[1]); mma16816(acc[1], hi, bb0[2], bb0[3]);
            mma16816(acc[2], hi, bb1[0], bb1[1]); mma16816(acc[3], hi, bb1[2], bb1[3]);
            mma16816(acc[0], lo, bb0[0], bb0[1]); mma16816(acc[1], lo, bb0[2], bb0[3]);
            mma16816(acc[2], lo, bb1[0], bb1[1]); mma16816(acc[3], lo, bb1[2], bb1[3]);
        }

        if (t + 1 < NTl) {
            stageB((t + 1) & 1);     // writes buf^1: its tile t-1 readers done pre-barrier
            if (t + 2 < NTl) loadAdj(t + 2);
        }
        __syncthreads();             // B(t+1) visible; tile-t reads complete
    }

    // ---- degrees: exact fp32, smem atomic reduction ----
    #pragma unroll
    for (int j = 0; j < 16; j++)
        atomicAdd(&degS[c16 * 16 + j], dacc[j]);

    // ---- stage accumulators (outS aliases B buffers; disjoint from degS) ----
    float* outS = (float*)smem;      // [m][c], stride 68 floats (17408 B)
    #pragma unroll
    for (int nb = 0; nb < 4; nb++) {
        int c_row = cblk * 16 + (lid >> 2);
        int m_col = wc * 32 + nb * 8 + (lid & 3) * 2;
        outS[m_col * 68 + c_row]           = acc[nb][0];
        outS[(m_col + 1) * 68 + c_row]     = acc[nb][1];
        outS[m_col * 68 + c_row + 8]       = acc[nb][2];
        outS[(m_col + 1) * 68 + c_row + 8] = acc[nb][3];
    }
    __syncthreads();

    // ---- scaled float4 stores ----
    float* Og = out + ((size_t)b * Mv + m0) * Cv;
    #pragma unroll
    for (int i = 0; i < 4; i++) {
        int idx = tid + i * 256;                 // 1024 float4s
        int ml = idx >> 4, c4 = (idx & 15) * 4;
        float4 v = *(float4*)(outS + ml * 68 + c4);
        float inv = __frcp_rn(fmaxf(degS[ml], 1.0f));
        v.x *= inv; v.y *= inv; v.z *= inv; v.w *= inv;
        *(float4*)(Og + (size_t)ml * Cv + c4) = v;
    }
}

extern "C" void kernel_launch(void* const* d_in, const int* in_sizes, int n_in,
                              void* d_out, int out_size)
{
    const float* x;
    const float* adj;
    if (in_sizes[0] == BZv * Cv * Nv) {
        x   = (const float*)d_in[0];
        adj = (const float*)d_in[1];
    } else {
        x   = (const float*)d_in[1];
        adj = (const float*)d_in[0];
    }
    float* out = (float*)d_out;

    prep_A<<<1024, 256>>>(x);                                // 262144 threads
    sg_kg_fp16<<<dim3(Mv / MTm, BZv), 256>>>(adj, out);      // 32 x 8 = 256 CTAs
}

// round 12
// speedup vs baseline: 1.6627x; 1.2549x over previous
#include <cuda_runtime.h>
#include <cuda_fp16.h>
#include <cstdint>

// SGIntoKGPool via mma.sync m16n8k16 fp16, SINGLE GEMM (x and adj both fp16-rn).
// out[b,m,c] = (sum_n adj[b,n,m] * x[b,c,n]) / max(sum_n adj[b,n,m], 1)
// B=8, C=64, N=4096, M=2048.
// Round 12: no hi/lo split (half the MMAs, half the A traffic/regs), 3 CTAs/SM.
// A frags direct LDG from fragment-order panels (one-tile-ahead refill),
// B = adj LDG -> fp32 degrees -> fp16 cvt -> STS -> ldmatrix.trans.

#define BZv 8
#define Cv  64
#define Nv  4096
#define Mv  2048
#define KT  64
#define NTl (Nv / KT)       // 64 k-tiles
#define MTm 64              // m-tile

#define APANEL   8192        // A tile panel bytes (fp16 fragment order)
#define BSTRIDE  144         // bytes per B smem row (64 halfs + 16B pad)
#define BBUF     (KT * BSTRIDE)             // 9216
#define OFF_DEGS (2 * BBUF)                 // 18432
#define SMEMB    (OFF_DEGS + 256)           // 18688 (static)

// x fp16 fragment panels: per (b,kt): 16 groups (cblk*4+ks) x 32 lanes x uint4 = 8KB
__device__ uint4 g_A[BZv * NTl * 512];      // 4 MB

__device__ __forceinline__ uint32_t smem_u32(const void* p) {
    uint32_t a;
    asm("{ .reg .u64 t; cvta.to.shared.u64 t, %1; cvt.u32.u64 %0, t; }" : "=r"(a) : "l"(p));
    return a;
}
__device__ __forceinline__ void ldsm4t(uint32_t (&r)[4], uint32_t a) {
    asm volatile("ldmatrix.sync.aligned.m8n8.x4.trans.shared.b16 {%0,%1,%2,%3}, [%4];"
                 : "=r"(r[0]), "=r"(r[1]), "=r"(r[2]), "=r"(r[3]) : "r"(a));
}
__device__ __forceinline__ void mma16816(float (&d)[4], const uint4& a,
                                         uint32_t b0, uint32_t b1) {
    asm volatile("mma.sync.aligned.m16n8k16.row.col.f32.f16.f16.f32 "
                 "{%0,%1,%2,%3}, {%4,%5,%6,%7}, {%8,%9}, {%0,%1,%2,%3};"
                 : "+f"(d[0]), "+f"(d[1]), "+f"(d[2]), "+f"(d[3])
                 : "r"(a.x), "r"(a.y), "r"(a.z), "r"(a.w), "r"(b0), "r"(b1));
}
__device__ __forceinline__ unsigned packh2(float v0, float v1) {
    __half h0 = __float2half_rn(v0), h1 = __float2half_rn(v1);
    return (unsigned)__half_as_ushort(h0) | ((unsigned)__half_as_ushort(h1) << 16);
}
__device__ __forceinline__ void sts128(uint32_t a, uint4 v) {
    asm volatile("st.shared.v4.b32 [%0], {%1,%2,%3,%4};"
                 :: "r"(a), "r"(v.x), "r"(v.y), "r"(v.z), "r"(v.w) : "memory");
}

// ---------------- prep: x -> fp16 fragment panels ----------------
// m16n8k16 A fragment: lane l holds rows {g, g+8} (g=l>>2), cols {2t,2t+1, +8} (t=l&3)
__global__ __launch_bounds__(256)
void prep_A(const float* __restrict__ x) {
    unsigned gid  = blockIdx.x * 256 + threadIdx.x;    // 262144 threads
    unsigned lid  = gid & 31;
    unsigned ks   = (gid >> 5) & 3;
    unsigned cblk = (gid >> 7) & 3;
    unsigned kt   = (gid >> 9) & (NTl - 1);
    unsigned b    = gid >> 15;

    int r0 = cblk * 16 + (lid >> 2);                   // c row
    const float* px = x + ((size_t)b * Cv + r0) * Nv + kt * KT + ks * 16 + (lid & 3) * 2;

    uint4 f;
    f.x = packh2(px[0],          px[1]);
    f.y = packh2(px[8 * Nv],     px[8 * Nv + 1]);
    f.z = packh2(px[8],          px[9]);
    f.w = packh2(px[8 * Nv + 8], px[8 * Nv + 9]);

    g_A[((size_t)(b * NTl + kt) << 9) + (cblk * 4 + ks) * 32 + lid] = f;
}

// ---------------- main kernel ----------------
__global__ __launch_bounds__(256, 3)
void sg_kg_fp16(const float* __restrict__ adj, float* __restrict__ out) {
    __shared__ __align__(16) char smem[SMEMB];
    const int tid = threadIdx.x;
    const int lid = tid & 31, wid = tid >> 5;
    const int b = blockIdx.y, m0 = blockIdx.x * MTm;
    const int cblk = wid & 3;        // c dir: 4 warps x 16 rows
    const int wc   = wid >> 2;       // m dir: 2 warps x 32 cols
    const uint32_t sb = smem_u32(smem);

    // adj lane mapping: thread owns k-rows r, r+32; m chunk mq*8..+7
    const int r  = tid >> 3;         // 0..31
    const int mq = tid & 7;
    const float* adjb = adj + (size_t)b * Nv * Mv + m0 + mq * 8;

    const char* Apan = (const char*)g_A + (size_t)(b * NTl) * APANEL + lid * 16;

    float* degS = (float*)(smem + OFF_DEGS);
    if (tid < MTm) degS[tid] = 0.0f;

    float acc[4][4];
    #pragma unroll
    for (int j = 0; j < 4; j++)
        #pragma unroll
        for (int p = 0; p < 4; p++) acc[j][p] = 0.f;
    float dacc[8] = {0,0,0,0,0,0,0,0};

    // B ldsm per-thread offset (+ks*16 rows per k-step)
    const uint32_t bl = (uint32_t)((lid & 15) * BSTRIDE + (wc * 32 + (lid >> 4) * 8) * 2);
    // A fragment byte offset: group g = cblk*4 + ks, offset g*512 (+lid*16 in Apan)
    const uint32_t ag = (uint32_t)(cblk * 4) * 512;

    float4 fr0, fr1, fr2, fr3;       // adj prefetch: rows r, r+32 x 8 m
    auto loadAdj = [&](int t) {
        const float* g = adjb + (size_t)(t * KT + r) * Mv;
        fr0 = *(const float4*)(g);
        fr1 = *(const float4*)(g + 4);
        const float* g2 = g + (size_t)32 * Mv;
        fr2 = *(const float4*)(g2);
        fr3 = *(const float4*)(g2 + 4);
    };
    auto stageB = [&](int bufsel) {
        dacc[0] += fr0.x + fr2.x; dacc[1] += fr0.y + fr2.y;
        dacc[2] += fr0.z + fr2.z; dacc[3] += fr0.w + fr2.w;
        dacc[4] += fr1.x + fr3.x; dacc[5] += fr1.y + fr3.y;
        dacc[6] += fr1.z + fr3.z; dacc[7] += fr1.w + fr3.w;
        uint32_t s = sb + bufsel * BBUF + r * BSTRIDE + mq * 16;
        uint4 w0 = make_uint4(packh2(fr0.x, fr0.y), packh2(fr0.z, fr0.w),
                              packh2(fr1.x, fr1.y), packh2(fr1.z, fr1.w));
        uint4 w1 = make_uint4(packh2(fr2.x, fr2.y), packh2(fr2.z, fr2.w),
                              packh2(fr3.x, fr3.y), packh2(fr3.z, fr3.w));
        sts128(s, w0);
        sts128(s + 32 * BSTRIDE, w1);
    };

    // A fragments for current tile (one uint4 per ks)
    uint4 afr[4];
    #pragma unroll
    for (int ks = 0; ks < 4; ks++)
        afr[ks] = *(const uint4*)(Apan + ag + ks * 512);

    // prologue
    loadAdj(0);
    stageB(0);
    __syncthreads();
    loadAdj(1);

    for (int t = 0; t < NTl; t++) {
        const char* Anext = Apan + (size_t)((t + 1 < NTl) ? t + 1 : t) * APANEL;
        const uint32_t sB = sb + (t & 1) * BBUF + bl;

        #pragma unroll
        for (int ks = 0; ks < 4; ks++) {
            uint32_t bb0[4], bb1[4];
            ldsm4t(bb0, sB + ks * (16 * BSTRIDE));         // n 0..15 of warp half
            ldsm4t(bb1, sB + ks * (16 * BSTRIDE) + 32);    // n 16..31
            uint4 a = afr[ks];
            afr[ks] = *(const uint4*)(Anext + ag + ks * 512);   // full-tile refill slack
            mma16816(acc[0], a, bb0[0], bb0[1]); mma16816(acc[1], a, bb0[2], bb0[3]);
            mma16816(acc[2], a, bb1[0], bb1[1]); mma16816(acc[3], a, bb1[2], bb1[3]);
        }

        if (t + 1 < NTl) {
            stageB((t + 1) & 1);     // buf^1: its tile t-1 readers finished pre-barrier
            if (t + 2 < NTl) loadAdj(t + 2);
        }
        __syncthreads();             // B(t+1) visible; tile-t reads complete
    }

    // ---- degrees: exact fp32, smem atomic reduction ----
    #pragma unroll
    for (int j = 0; j < 4; j++) {
        atomicAdd(&degS[mq * 8 + j],     dacc[j]);
        atomicAdd(&degS[mq * 8 + 4 + j], dacc[4 + j]);
    }

    // ---- stage accumulators (outS aliases B buffers; disjoint from degS) ----
    float* outS = (float*)smem;      // [m][c], stride 68 floats (17408 B)
    #pragma unroll
    for (int nb = 0; nb < 4; nb++) {
        int c_row = cblk * 16 + (lid >> 2);
        int m_col = wc * 32 + nb * 8 + (lid & 3) * 2;
        outS[m_col * 68 + c_row]           = acc[nb][0];
        outS[(m_col + 1) * 68 + c_row]     = acc[nb][1];
        outS[m_col * 68 + c_row + 8]       = acc[nb][2];
        outS[(m_col + 1) * 68 + c_row + 8] = acc[nb][3];
    }
    __syncthreads();

    // ---- scaled float4 stores ----
    float* Og = out + ((size_t)b * Mv + m0) * Cv;
    #pragma unroll
    for (int i = 0; i < 4; i++) {
        int idx = tid + i * 256;                 // 1024 float4s
        int ml = idx >> 4, c4 = (idx & 15) * 4;
        float4 v = *(float4*)(outS + ml * 68 + c4);
        float inv = __frcp_rn(fmaxf(degS[ml], 1.0f));
        v.x *= inv; v.y *= inv; v.z *= inv; v.w *= inv;
        *(float4*)(Og + (size_t)ml * Cv + c4) = v;
    }
}

extern "C" void kernel_launch(void* const* d_in, const int* in_sizes, int n_in,
                              void* d_out, int out_size)
{
    const float* x;
    const float* adj;
    if (in_sizes[0] == BZv * Cv * Nv) {
        x   = (const float*)d_in[0];
        adj = (const float*)d_in[1];
    } else {
        x   = (const float*)d_in[1];
        adj = (const float*)d_in[0];
    }
    float* out = (float*)d_out;

    prep_A<<<1024, 256>>>(x);                                // 262144 threads
    sg_kg_fp16<<<dim3(Mv / MTm, BZv), 256>>>(adj, out);      // 32 x 8 = 256 CTAs
}